// round 2
// baseline (speedup 1.0000x reference)
#include <cuda_runtime.h>
#include <cuda_bf16.h>

// Problem constants (fixed by the reference)
#define BATCH   2
#define NPTS    8192
#define DIM     32
#define R2      0.0009f     // 0.03^2
#define SIMT    0.7f
#define EPSN    1e-8f
#define MINLEAF 10

#define TPB   64            // threads per block in main kernel (1 i per thread)
#define TILE  1024          // j points cached in smem per tile

// Scratch (static __device__ — no allocations allowed)
__device__ float  g_en[BATCH * NPTS * DIM];   // normalized embeddings (2 MB)
__device__ float4 g_pts[BATCH * NPTS];        // (x,y,z,leafflag); non-leaf coords = 1e9
__device__ int    g_leafcnt[BATCH];

__global__ void zero_kernel() {
    if (threadIdx.x < BATCH) g_leafcnt[threadIdx.x] = 0;
}

__global__ void prep_kernel(const float* __restrict__ points,
                            const float* __restrict__ emb,
                            const int*   __restrict__ leaf) {
    int idx = blockIdx.x * blockDim.x + threadIdx.x;
    if (idx >= BATCH * NPTS) return;

    // normalized embedding with clamped norm (matches reference eps semantics)
    const float4* e4 = (const float4*)(emb + (size_t)idx * DIM);
    float v[DIM];
    float s = 0.f;
#pragma unroll
    for (int q = 0; q < DIM / 4; q++) {
        float4 t = __ldg(e4 + q);
        v[4*q+0] = t.x; v[4*q+1] = t.y; v[4*q+2] = t.z; v[4*q+3] = t.w;
        s = fmaf(t.x, t.x, s); s = fmaf(t.y, t.y, s);
        s = fmaf(t.z, t.z, s); s = fmaf(t.w, t.w, s);
    }
    float inv = 1.f / fmaxf(sqrtf(s), EPSN);
    float4* o4 = (float4*)(g_en + (size_t)idx * DIM);
#pragma unroll
    for (int q = 0; q < DIM / 4; q++) {
        o4[q] = make_float4(v[4*q] * inv, v[4*q+1] * inv, v[4*q+2] * inv, v[4*q+3] * inv);
    }

    // packed point with leaf folded into geometry
    int lf = leaf[idx] > 0;
    float4 p;
    if (lf) p = make_float4(points[3*(size_t)idx], points[3*(size_t)idx+1],
                            points[3*(size_t)idx+2], 1.f);
    else    p = make_float4(1e9f, 1e9f, 1e9f, 0.f);
    g_pts[idx] = p;

    // per-batch leaf count (warp is batch-homogeneous: NPTS % 32 == 0)
    unsigned msk = __ballot_sync(0xffffffffu, lf);
    if ((threadIdx.x & 31) == 0)
        atomicAdd(&g_leafcnt[idx / NPTS], __popc(msk));
}

__global__ void __launch_bounds__(TPB)
main_kernel(const float* __restrict__ points,
            const float* __restrict__ emb,
            const int*   __restrict__ leaf,
            const float* __restrict__ W1,
            const float* __restrict__ b1,
            const float* __restrict__ W2,
            const float* __restrict__ b2,
            float* __restrict__ out) {
    __shared__ float4 s_tile[TILE];
    __shared__ float  sW1[2 * DIM * DIM];
    __shared__ float  sW2[DIM * DIM];
    __shared__ float  sb1[DIM];
    __shared__ float  sb2[DIM];

    const int bpB = NPTS / TPB;
    const int b = blockIdx.x / bpB;
    const int i = (blockIdx.x % bpB) * TPB + threadIdx.x;
    const size_t gi = (size_t)b * NPTS + i;

    // stage MLP weights (used only in epilogue; syncthreads inside j-loop covers the hazard)
    for (int t = threadIdx.x; t < 2 * DIM * DIM; t += TPB) sW1[t] = W1[t];
    for (int t = threadIdx.x; t < DIM * DIM; t += TPB)     sW2[t] = W2[t];
    if (threadIdx.x < DIM) { sb1[threadIdx.x] = b1[threadIdx.x]; sb2[threadIdx.x] = b2[threadIdx.x]; }

    // own (raw) point — reference computes nb for every i, leaf or not
    const float xi = points[3 * gi], yi = points[3 * gi + 1], zi = points[3 * gi + 2];

    // own normalized embedding (kept in regs for the sim dot)
    float eni[DIM];
    {
        const float4* e4 = (const float4*)(emb + gi * DIM);
        float s = 0.f;
#pragma unroll
        for (int q = 0; q < 8; q++) {
            float4 t = __ldg(e4 + q);
            eni[4*q] = t.x; eni[4*q+1] = t.y; eni[4*q+2] = t.z; eni[4*q+3] = t.w;
            s = fmaf(t.x, t.x, s); s = fmaf(t.y, t.y, s);
            s = fmaf(t.z, t.z, s); s = fmaf(t.w, t.w, s);
        }
        float inv = 1.f / fmaxf(sqrtf(s), EPSN);
#pragma unroll
        for (int k = 0; k < DIM; k++) eni[k] *= inv;
    }

    float acc[DIM];
#pragma unroll
    for (int k = 0; k < DIM; k++) acc[k] = 0.f;
    int nbcnt = 0, cnt = 0;

    const float*  enb  = g_en  + (size_t)b * NPTS * DIM;
    const float*  embb = emb   + (size_t)b * NPTS * DIM;
    const float4* pb   = g_pts + (size_t)b * NPTS;

    for (int t0 = 0; t0 < NPTS; t0 += TILE) {
        for (int t = threadIdx.x; t < TILE; t += TPB) s_tile[t] = __ldg(pb + t0 + t);
        __syncthreads();
#pragma unroll 4
        for (int jj = 0; jj < TILE; jj++) {
            // broadcast LDS.128 — all lanes read the same j
            float4 p = s_tile[jj];
            float dx = xi - p.x, dy = yi - p.y, dz = zi - p.z;
            float d2 = fmaf(dx, dx, fmaf(dy, dy, dz * dz));
            if (d2 < R2) {               // rare (~0.18% per lane): includes leaf[j] via 1e9 fold
                nbcnt++;
                int j = t0 + jj;
                const float4* ej = (const float4*)(enb + (size_t)j * DIM);
                float dot = 0.f;
#pragma unroll
                for (int q = 0; q < 8; q++) {
                    float4 v = __ldg(ej + q);
                    dot = fmaf(v.x, eni[4*q],   dot);
                    dot = fmaf(v.y, eni[4*q+1], dot);
                    dot = fmaf(v.z, eni[4*q+2], dot);
                    dot = fmaf(v.w, eni[4*q+3], dot);
                }
                if (dot > SIMT) {        // essentially only self: accumulate RAW embedding (exact)
                    cnt++;
                    const float4* rj = (const float4*)(embb + (size_t)j * DIM);
#pragma unroll
                    for (int q = 0; q < 8; q++) {
                        float4 v = __ldg(rj + q);
                        acc[4*q]   += v.x;
                        acc[4*q+1] += v.y;
                        acc[4*q+2] += v.z;
                        acc[4*q+3] += v.w;
                    }
                }
            }
        }
        __syncthreads();
    }

    // ---- epilogue: MLP + select ----
    float rinv = 1.f / (float)(cnt > 1 ? cnt : 1);

    // reload raw e_i (L1/L2 hit) — kept out of the hot loop to cap register pressure
    float ei[DIM];
    {
        const float4* e4 = (const float4*)(emb + gi * DIM);
#pragma unroll
        for (int q = 0; q < 8; q++) {
            float4 t = __ldg(e4 + q);
            ei[4*q] = t.x; ei[4*q+1] = t.y; ei[4*q+2] = t.z; ei[4*q+3] = t.w;
        }
    }

    float h[DIM];
#pragma unroll
    for (int o = 0; o < DIM; o++) h[o] = sb1[o];
#pragma unroll 4
    for (int k = 0; k < 2 * DIM; k++) {
        float c = (k < DIM) ? ei[k] : acc[k - DIM] * rinv;
        const float* wrow = &sW1[k * DIM];   // broadcast smem reads
#pragma unroll
        for (int o = 0; o < DIM; o++) h[o] = fmaf(c, wrow[o], h[o]);
    }
#pragma unroll
    for (int o = 0; o < DIM; o++) h[o] = fmaxf(h[o], 0.f);

    float ov[DIM];
#pragma unroll
    for (int o = 0; o < DIM; o++) ov[o] = sb2[o];
#pragma unroll 4
    for (int k = 0; k < DIM; k++) {
        float c = h[k];
        const float* wrow = &sW2[k * DIM];
#pragma unroll
        for (int o = 0; o < DIM; o++) ov[o] = fmaf(c, wrow[o], ov[o]);
    }

    bool cond = (leaf[gi] > 0) && (nbcnt > 1) && (cnt > 0) && (g_leafcnt[b] >= MINLEAF);

    float4* o4 = (float4*)(out + gi * DIM);
#pragma unroll
    for (int q = 0; q < 8; q++) {
        float4 t = cond ? make_float4(ov[4*q], ov[4*q+1], ov[4*q+2], ov[4*q+3])
                        : make_float4(ei[4*q], ei[4*q+1], ei[4*q+2], ei[4*q+3]);
        o4[q] = t;
    }
}

extern "C" void kernel_launch(void* const* d_in, const int* in_sizes, int n_in,
                              void* d_out, int out_size) {
    const float* points = (const float*)d_in[0];
    const float* emb    = (const float*)d_in[1];
    const int*   leaf   = (const int*)d_in[2];
    const float* W1     = (const float*)d_in[3];
    const float* b1     = (const float*)d_in[4];
    const float* W2     = (const float*)d_in[5];
    const float* b2     = (const float*)d_in[6];
    float* out = (float*)d_out;

    zero_kernel<<<1, 32>>>();
    prep_kernel<<<(BATCH * NPTS + 127) / 128, 128>>>(points, emb, leaf);
    main_kernel<<<BATCH * (NPTS / TPB), TPB>>>(points, emb, leaf, W1, b1, W2, b2, out);
}

// round 3
// speedup vs baseline: 3.5291x; 3.5291x over previous
#include <cuda_runtime.h>
#include <cuda_bf16.h>

// Problem constants (fixed by the reference)
#define BATCH   2
#define NPTS    8192
#define DIM     32
#define R2      0.0009f     // 0.03^2
#define SIMT    0.7f
#define EPSN    1e-8f
#define MINLEAF 10

#define GRIDC   14                      // ceil(0.4 / 0.03)
#define NCELL   (GRIDC * GRIDC * GRIDC) // 2744
#define CAP     32                      // bucket capacity (mean occupancy ~1.5)
#define INVC    33.333332f              // 1 / 0.03
#define MARGIN  0.0302f                 // radius + safety margin for cell-range bound

#define TPB     128

// Scratch (static __device__ — no allocations allowed)
__device__ float  g_en[BATCH * NPTS * DIM];          // normalized embeddings (2 MB)
__device__ int    g_cellcnt[BATCH * NCELL];          // points per cell
__device__ float4 g_bucket[BATCH * NCELL * CAP];     // (x,y,z, bitcast local idx)
__device__ int    g_leafcnt[BATCH];

__global__ void zero_kernel() {
    int t = blockIdx.x * blockDim.x + threadIdx.x;
    if (t < BATCH * NCELL) g_cellcnt[t] = 0;
    if (t < BATCH)         g_leafcnt[t] = 0;
}

__global__ void prep_kernel(const float* __restrict__ points,
                            const float* __restrict__ emb,
                            const int*   __restrict__ leaf) {
    int idx = blockIdx.x * blockDim.x + threadIdx.x;
    if (idx >= BATCH * NPTS) return;
    int b = idx / NPTS;
    int j = idx - b * NPTS;

    // normalized embedding with clamped norm (matches reference eps semantics)
    const float4* e4 = (const float4*)(emb + (size_t)idx * DIM);
    float v[DIM];
    float s = 0.f;
#pragma unroll
    for (int q = 0; q < DIM / 4; q++) {
        float4 t = __ldg(e4 + q);
        v[4*q+0] = t.x; v[4*q+1] = t.y; v[4*q+2] = t.z; v[4*q+3] = t.w;
        s = fmaf(t.x, t.x, s); s = fmaf(t.y, t.y, s);
        s = fmaf(t.z, t.z, s); s = fmaf(t.w, t.w, s);
    }
    float inv = 1.f / fmaxf(sqrtf(s), EPSN);
    float4* o4 = (float4*)(g_en + (size_t)idx * DIM);
#pragma unroll
    for (int q = 0; q < DIM / 4; q++)
        o4[q] = make_float4(v[4*q] * inv, v[4*q+1] * inv, v[4*q+2] * inv, v[4*q+3] * inv);

    // leaf count + grid insert (only leaf points can be neighbors)
    int lf = leaf[idx] > 0;
    unsigned msk = __ballot_sync(0xffffffffu, lf);
    if ((threadIdx.x & 31) == 0 && msk)
        atomicAdd(&g_leafcnt[b], __popc(msk));

    if (lf) {
        float x = points[3 * (size_t)idx];
        float y = points[3 * (size_t)idx + 1];
        float z = points[3 * (size_t)idx + 2];
        int cx = min(GRIDC - 1, (int)(x * INVC));
        int cy = min(GRIDC - 1, (int)(y * INVC));
        int cz = min(GRIDC - 1, (int)(z * INVC));
        int c = b * NCELL + (cz * GRIDC + cy) * GRIDC + cx;
        int pos = atomicAdd(&g_cellcnt[c], 1);
        if (pos < CAP)
            g_bucket[(size_t)c * CAP + pos] = make_float4(x, y, z, __int_as_float(j));
    }
}

__global__ void __launch_bounds__(TPB)
query_kernel(const float* __restrict__ points,
             const float* __restrict__ emb,
             const int*   __restrict__ leaf,
             const float* __restrict__ W1,
             const float* __restrict__ b1,
             const float* __restrict__ W2,
             const float* __restrict__ b2,
             float* __restrict__ out) {
    __shared__ int   s_cnt[NCELL];          // this batch's per-cell counts (11 KB)
    __shared__ float sW1[2 * DIM * DIM];
    __shared__ float sW2[DIM * DIM];
    __shared__ float sb1[DIM];
    __shared__ float sb2[DIM];

    const int bpB = NPTS / TPB;                 // 64 blocks per batch
    const int b = blockIdx.x / bpB;
    const int i = (blockIdx.x % bpB) * TPB + threadIdx.x;
    const size_t gi = (size_t)b * NPTS + i;

    for (int t = threadIdx.x; t < NCELL; t += TPB)          s_cnt[t] = g_cellcnt[b * NCELL + t];
    for (int t = threadIdx.x; t < 2 * DIM * DIM; t += TPB)  sW1[t] = W1[t];
    for (int t = threadIdx.x; t < DIM * DIM; t += TPB)      sW2[t] = W2[t];
    if (threadIdx.x < DIM) { sb1[threadIdx.x] = b1[threadIdx.x]; sb2[threadIdx.x] = b2[threadIdx.x]; }
    __syncthreads();

    // own raw point — reference tests nb for every i, leaf or not
    const float xi = points[3 * gi], yi = points[3 * gi + 1], zi = points[3 * gi + 2];

    // own normalized embedding (prep wrote it; L2 hit)
    float eni[DIM];
    {
        const float4* e4 = (const float4*)(g_en + gi * DIM);
#pragma unroll
        for (int q = 0; q < 8; q++) {
            float4 t = __ldg(e4 + q);
            eni[4*q] = t.x; eni[4*q+1] = t.y; eni[4*q+2] = t.z; eni[4*q+3] = t.w;
        }
    }

    float acc[DIM];
#pragma unroll
    for (int k = 0; k < DIM; k++) acc[k] = 0.f;
    int nbcnt = 0, cnt = 0;

    const float* enb  = g_en + (size_t)b * NPTS * DIM;
    const float* embb = emb  + (size_t)b * NPTS * DIM;

    // cell range covering the open ball of radius 0.03 (margin >> fp rounding)
    int cx0 = max(0, (int)((xi - MARGIN) * INVC)), cx1 = min(GRIDC - 1, (int)((xi + MARGIN) * INVC));
    int cy0 = max(0, (int)((yi - MARGIN) * INVC)), cy1 = min(GRIDC - 1, (int)((yi + MARGIN) * INVC));
    int cz0 = max(0, (int)((zi - MARGIN) * INVC)), cz1 = min(GRIDC - 1, (int)((zi + MARGIN) * INVC));

    for (int cz = cz0; cz <= cz1; cz++) {
        for (int cy = cy0; cy <= cy1; cy++) {
            int rowc = (cz * GRIDC + cy) * GRIDC;
            for (int cx = cx0; cx <= cx1; cx++) {
                int c = rowc + cx;
                int n = min(s_cnt[c], CAP);
                const float4* bk = g_bucket + ((size_t)b * NCELL + c) * CAP;
                for (int k = 0; k < n; k++) {
                    float4 p = __ldg(bk + k);
                    float dx = xi - p.x, dy = yi - p.y, dz = zi - p.z;
                    float d2 = fmaf(dx, dx, fmaf(dy, dy, dz * dz));
                    if (d2 < R2) {
                        nbcnt++;
                        int j = __float_as_int(p.w);
                        const float4* ej = (const float4*)(enb + (size_t)j * DIM);
                        float dot = 0.f;
#pragma unroll
                        for (int q = 0; q < 8; q++) {
                            float4 v = __ldg(ej + q);
                            dot = fmaf(v.x, eni[4*q],   dot);
                            dot = fmaf(v.y, eni[4*q+1], dot);
                            dot = fmaf(v.z, eni[4*q+2], dot);
                            dot = fmaf(v.w, eni[4*q+3], dot);
                        }
                        if (dot > SIMT) {     // accumulate RAW embedding (exact semantics)
                            cnt++;
                            const float4* rj = (const float4*)(embb + (size_t)j * DIM);
#pragma unroll
                            for (int q = 0; q < 8; q++) {
                                float4 v = __ldg(rj + q);
                                acc[4*q]   += v.x;
                                acc[4*q+1] += v.y;
                                acc[4*q+2] += v.z;
                                acc[4*q+3] += v.w;
                            }
                        }
                    }
                }
            }
        }
    }

    // ---- epilogue: MLP + select (identical to rel_err==0.0 R2 kernel) ----
    float rinv = 1.f / (float)(cnt > 1 ? cnt : 1);

    float ei[DIM];
    {
        const float4* e4 = (const float4*)(emb + gi * DIM);
#pragma unroll
        for (int q = 0; q < 8; q++) {
            float4 t = __ldg(e4 + q);
            ei[4*q] = t.x; ei[4*q+1] = t.y; ei[4*q+2] = t.z; ei[4*q+3] = t.w;
        }
    }

    float h[DIM];
#pragma unroll
    for (int o = 0; o < DIM; o++) h[o] = sb1[o];
#pragma unroll 4
    for (int k = 0; k < 2 * DIM; k++) {
        float c = (k < DIM) ? ei[k] : acc[k - DIM] * rinv;
        const float* wrow = &sW1[k * DIM];   // broadcast smem reads
#pragma unroll
        for (int o = 0; o < DIM; o++) h[o] = fmaf(c, wrow[o], h[o]);
    }
#pragma unroll
    for (int o = 0; o < DIM; o++) h[o] = fmaxf(h[o], 0.f);

    float ov[DIM];
#pragma unroll
    for (int o = 0; o < DIM; o++) ov[o] = sb2[o];
#pragma unroll 4
    for (int k = 0; k < DIM; k++) {
        float c = h[k];
        const float* wrow = &sW2[k * DIM];
#pragma unroll
        for (int o = 0; o < DIM; o++) ov[o] = fmaf(c, wrow[o], ov[o]);
    }

    bool cond = (leaf[gi] > 0) && (nbcnt > 1) && (cnt > 0) && (g_leafcnt[b] >= MINLEAF);

    float4* o4 = (float4*)(out + gi * DIM);
#pragma unroll
    for (int q = 0; q < 8; q++) {
        float4 t = cond ? make_float4(ov[4*q], ov[4*q+1], ov[4*q+2], ov[4*q+3])
                        : make_float4(ei[4*q], ei[4*q+1], ei[4*q+2], ei[4*q+3]);
        o4[q] = t;
    }
}

extern "C" void kernel_launch(void* const* d_in, const int* in_sizes, int n_in,
                              void* d_out, int out_size) {
    const float* points = (const float*)d_in[0];
    const float* emb    = (const float*)d_in[1];
    const int*   leaf   = (const int*)d_in[2];
    const float* W1     = (const float*)d_in[3];
    const float* b1     = (const float*)d_in[4];
    const float* W2     = (const float*)d_in[5];
    const float* b2     = (const float*)d_in[6];
    float* out = (float*)d_out;

    zero_kernel<<<(BATCH * NCELL + 255) / 256, 256>>>();
    prep_kernel<<<(BATCH * NPTS + TPB - 1) / TPB, TPB>>>(points, emb, leaf);
    query_kernel<<<BATCH * (NPTS / TPB), TPB>>>(points, emb, leaf, W1, b1, W2, b2, out);
}